// round 3
// baseline (speedup 1.0000x reference)
#include <cuda_runtime.h>
#include <math.h>

#define N_NODES 50000
#define H 8
#define D 32
#define DEG 16
#define HD (H * D)            // 256
#define NPB 4                 // nodes per block

// ---------------------------------------------------------------------------
// Single fused kernel: 256-thread block = 4 nodes x 64 threads.
// Edges of node n are [16n, 16n+16) since dst = repeat(arange(N), DEG).
//
// Thread (node, u): h = u>>3 (head), lo3 = u&7 (float4 slice within head).
// 1. Load 16 src ids (int4 x4, L1-broadcast within node group).
// 2. Load dst row slice -> er via 8-lane butterfly.
// 3. Load all 16 src row slices (LDG.128, warp = 512B contiguous per edge)
//    and KEEP them in registers.
// 4. Per-lane partial dots with attn_l, packed fold-reduction (14 shuffles)
//    -> lane lo3 owns logits j = 2*lo3, 2*lo3+1.
// 5. LeakyReLU + 8-lane softmax (max/sum butterflies, 2 exps per lane).
// 6. Publish 16 attn weights via smem + __syncwarp (head group is intra-warp).
// 7. Weighted accumulate from the registers of step 3, + bias, STG.128.
// No __syncthreads anywhere; no precompute kernel; one pass over feat.
// ---------------------------------------------------------------------------
__global__ __launch_bounds__(256) void gat_fused(
        const float* __restrict__ feat,
        const float* __restrict__ attn_l,
        const float* __restrict__ attn_r,
        const float* __restrict__ bias,
        const int*   __restrict__ src,
        float* __restrict__ out) {
    const int t    = threadIdx.x;
    const int node = t >> 6;               // 0..3
    const int u    = t & 63;
    const int h    = u >> 3;               // 0..7
    const int lo3  = u & 7;                // float4 slice id
    const int n    = blockIdx.x * NPB + node;

    __shared__ __align__(16) float s_a[NPB][H][DEG];

    const int off = h * D + lo3 * 4;       // float offset within a 256-float row

    // ---- 1. src indices (64B region per node, L1 broadcast) ----------------
    int sj[DEG];
    {
        const int4* sp = reinterpret_cast<const int4*>(src + n * DEG);
#pragma unroll
        for (int q = 0; q < 4; q++) {
            int4 v4 = sp[q];
            sj[4 * q + 0] = v4.x; sj[4 * q + 1] = v4.y;
            sj[4 * q + 2] = v4.z; sj[4 * q + 3] = v4.w;
        }
    }

    const float4 al4 = *reinterpret_cast<const float4*>(attn_l + off);
    const float4 ar4 = *reinterpret_cast<const float4*>(attn_r + off);

    // ---- 2. er(dst, h) ------------------------------------------------------
    float er;
    {
        float4 w = *reinterpret_cast<const float4*>(feat + (size_t)n * HD + off);
        float p = w.x * ar4.x + w.y * ar4.y + w.z * ar4.z + w.w * ar4.w;
        p += __shfl_xor_sync(0xffffffffu, p, 4);
        p += __shfl_xor_sync(0xffffffffu, p, 2);
        p += __shfl_xor_sync(0xffffffffu, p, 1);
        er = p;
    }

    // ---- 3. gather all 16 src row slices (kept in registers) ---------------
    float4 v[DEG];
#pragma unroll
    for (int j = 0; j < DEG; j++)
        v[j] = *reinterpret_cast<const float4*>(feat + (size_t)sj[j] * HD + off);

    // ---- 4. el partial dots + packed fold reduction -------------------------
    float p[DEG];
#pragma unroll
    for (int j = 0; j < DEG; j++)
        p[j] = v[j].x * al4.x + v[j].y * al4.y + v[j].z * al4.z + v[j].w * al4.w;

    const bool b2 = (lo3 & 4) != 0;
    const bool b1 = (lo3 & 2) != 0;
    const bool b0 = (lo3 & 1) != 0;

    float o8[8];
#pragma unroll
    for (int q = 0; q < 8; q++) {
        float send = b2 ? p[q] : p[q + 8];
        float recv = __shfl_xor_sync(0xffffffffu, send, 4);
        o8[q] = (b2 ? p[q + 8] : p[q]) + recv;      // j = q + 8*b2
    }
    float o4[4];
#pragma unroll
    for (int q = 0; q < 4; q++) {
        float send = b1 ? o8[q] : o8[q + 4];
        float recv = __shfl_xor_sync(0xffffffffu, send, 2);
        o4[q] = (b1 ? o8[q + 4] : o8[q]) + recv;    // j = q + 4*b1 + 8*b2
    }
    float o2[2];
#pragma unroll
    for (int q = 0; q < 2; q++) {
        float send = b0 ? o4[q] : o4[q + 2];
        float recv = __shfl_xor_sync(0xffffffffu, send, 1);
        o2[q] = (b0 ? o4[q + 2] : o4[q]) + recv;    // j = 2*lo3 + q
    }

    // ---- 5. leaky relu + softmax over the 16 edges (this head group) -------
    float e0 = o2[0] + er;
    float e1 = o2[1] + er;
    e0 = (e0 > 0.f) ? e0 : 0.2f * e0;
    e1 = (e1 > 0.f) ? e1 : 0.2f * e1;

    float m = fmaxf(e0, e1);
    m = fmaxf(m, __shfl_xor_sync(0xffffffffu, m, 4));
    m = fmaxf(m, __shfl_xor_sync(0xffffffffu, m, 2));
    m = fmaxf(m, __shfl_xor_sync(0xffffffffu, m, 1));

    float x0 = __expf(e0 - m);
    float x1 = __expf(e1 - m);
    float s  = x0 + x1;
    s += __shfl_xor_sync(0xffffffffu, s, 4);
    s += __shfl_xor_sync(0xffffffffu, s, 2);
    s += __shfl_xor_sync(0xffffffffu, s, 1);
    const float inv = 1.f / s;

    // ---- 6. publish attention weights (intra-warp only) --------------------
    *reinterpret_cast<float2*>(&s_a[node][h][2 * lo3]) =
        make_float2(x0 * inv, x1 * inv);
    __syncwarp();

    float av[DEG];
    {
        const float4* ap = reinterpret_cast<const float4*>(s_a[node][h]);
#pragma unroll
        for (int q = 0; q < 4; q++) {
            float4 a4 = ap[q];
            av[4 * q + 0] = a4.x; av[4 * q + 1] = a4.y;
            av[4 * q + 2] = a4.z; av[4 * q + 3] = a4.w;
        }
    }

    // ---- 7. weighted accumulate from registers + bias -----------------------
    float4 acc = *reinterpret_cast<const float4*>(bias + off);
#pragma unroll
    for (int j = 0; j < DEG; j++) {
        const float a = av[j];
        acc.x += a * v[j].x;
        acc.y += a * v[j].y;
        acc.z += a * v[j].z;
        acc.w += a * v[j].w;
    }
    *reinterpret_cast<float4*>(out + (size_t)n * HD + off) = acc;
}

// ---------------------------------------------------------------------------
extern "C" void kernel_launch(void* const* d_in, const int* in_sizes, int n_in,
                              void* d_out, int out_size) {
    const float* feat   = (const float*)d_in[0];
    const float* attn_l = (const float*)d_in[1];
    const float* attn_r = (const float*)d_in[2];
    const float* bias   = (const float*)d_in[3];
    const int*   src    = (const int*)d_in[4];
    // d_in[5] = dst: structurally repeat(arange(N), DEG); not needed.

    float* out = (float*)d_out;

    gat_fused<<<N_NODES / NPB, 256>>>(feat, attn_l, attn_r, bias, src, out);
}

// round 4
// speedup vs baseline: 1.3754x; 1.3754x over previous
#include <cuda_runtime.h>
#include <math.h>

#define N_NODES 50000
#define H 8
#define D 32
#define DEG 16
#define HD (H * D)            // 256
#define NH (N_NODES * H)
#define NPB 4                 // nodes per block in aggregate kernel

// Scratch for precomputed attention dot-products (no cudaMalloc allowed).
__device__ float g_el[NH];
__device__ float g_er[NH];

__device__ __forceinline__ float dot4(float4 a, float4 b) {
    return a.x * b.x + a.y * b.y + a.z * b.z + a.w * b.w;
}

// ---------------------------------------------------------------------------
// Kernel 1: one warp per node, fully coalesced.
// Lane l loads float4 #l and #(l+32) of the node's 256-float row
// (two contiguous 512B warp transactions). float4 index f -> head h = f>>3.
// Butterfly over 8-lane groups reduces the 4 partial dots; lanes 0..3 of each
// group scatter el[h], el[h+4], er[h], er[h+4].
// ---------------------------------------------------------------------------
__global__ __launch_bounds__(256) void precompute_dots(
        const float* __restrict__ feat,
        const float* __restrict__ attn_l,
        const float* __restrict__ attn_r) {
    const int gw   = (blockIdx.x * blockDim.x + threadIdx.x) >> 5;  // node
    const int lane = threadIdx.x & 31;
    if (gw >= N_NODES) return;

    const float4* f4 = reinterpret_cast<const float4*>(feat) + (size_t)gw * 64;
    const float4* al = reinterpret_cast<const float4*>(attn_l);
    const float4* ar = reinterpret_cast<const float4*>(attn_r);

    const float4 f0 = f4[lane];
    const float4 f1 = f4[lane + 32];
    const float4 a0 = al[lane], a1 = al[lane + 32];
    const float4 b0 = ar[lane], b1 = ar[lane + 32];

    float pl0 = dot4(f0, a0);   // partial el for head g   (g = lane>>3)
    float pl1 = dot4(f1, a1);   // partial el for head g+4
    float pr0 = dot4(f0, b0);   // partial er for head g
    float pr1 = dot4(f1, b1);   // partial er for head g+4

#pragma unroll
    for (int m = 4; m >= 1; m >>= 1) {
        pl0 += __shfl_xor_sync(0xffffffffu, pl0, m);
        pl1 += __shfl_xor_sync(0xffffffffu, pl1, m);
        pr0 += __shfl_xor_sync(0xffffffffu, pr0, m);
        pr1 += __shfl_xor_sync(0xffffffffu, pr1, m);
    }

    const int g    = lane >> 3;       // 0..3
    const int lo   = lane & 7;
    const int base = gw * H;
    if      (lo == 0) g_el[base + g]     = pl0;
    else if (lo == 1) g_el[base + g + 4] = pl1;
    else if (lo == 2) g_er[base + g]     = pr0;
    else if (lo == 3) g_er[base + g + 4] = pr1;
}

// ---------------------------------------------------------------------------
// Kernel 2: 256-thread block handles 4 nodes (64 threads / node).
// Edges of node n are [16n, 16n+16) since dst = repeat(arange(N), DEG).
// (unchanged from the 57.8us round-2 version)
// ---------------------------------------------------------------------------
__global__ __launch_bounds__(256) void gat_aggregate(
        const float* __restrict__ feat,
        const float* __restrict__ bias,
        const int*   __restrict__ src,
        float* __restrict__ out) {
    const int t    = threadIdx.x;
    const int n0   = blockIdx.x * NPB;
    const int node = t >> 6;     // 0..3
    const int u    = t & 63;
    const int h    = u >> 3;     // 0..7
    const int lo3  = u & 7;      // jj (phase B) / d4 (phase C)

    __shared__ int   s_src[NPB][DEG];
    __shared__ __align__(16) float s_a[NPB][H][DEG];

    // ---- Phase A: stage the 64 src indices -------------------------------
    if (t < NPB * DEG) {
        ((int*)s_src)[t] = src[n0 * DEG + t];
    }
    __syncthreads();

    // ---- Phase B: logits + shuffle softmax -------------------------------
    {
        const int n  = n0 + node;
        const float er_v = g_er[n * H + h];
        const int s0 = s_src[node][lo3];
        const int s1 = s_src[node][lo3 + 8];
        float e0 = g_el[s0 * H + h] + er_v;
        float e1 = g_el[s1 * H + h] + er_v;
        e0 = (e0 > 0.f) ? e0 : 0.2f * e0;
        e1 = (e1 > 0.f) ? e1 : 0.2f * e1;

        float m = fmaxf(e0, e1);
        m = fmaxf(m, __shfl_xor_sync(0xffffffffu, m, 4));
        m = fmaxf(m, __shfl_xor_sync(0xffffffffu, m, 2));
        m = fmaxf(m, __shfl_xor_sync(0xffffffffu, m, 1));

        float x0 = __expf(e0 - m);
        float x1 = __expf(e1 - m);
        float s  = x0 + x1;
        s += __shfl_xor_sync(0xffffffffu, s, 4);
        s += __shfl_xor_sync(0xffffffffu, s, 2);
        s += __shfl_xor_sync(0xffffffffu, s, 1);
        const float inv = 1.f / s;

        s_a[node][h][lo3]     = x0 * inv;
        s_a[node][h][lo3 + 8] = x1 * inv;
    }
    __syncthreads();

    // ---- Phase C: weighted float4 gather-aggregate ------------------------
    {
        float av[DEG];
        {
            const float4* ap = reinterpret_cast<const float4*>(s_a[node][h]);
#pragma unroll
            for (int q = 0; q < 4; q++) {
                float4 v = ap[q];
                av[q * 4 + 0] = v.x; av[q * 4 + 1] = v.y;
                av[q * 4 + 2] = v.z; av[q * 4 + 3] = v.w;
            }
        }
        int sj[DEG];
        {
            const int4* sp = reinterpret_cast<const int4*>(s_src[node]);
#pragma unroll
            for (int q = 0; q < 4; q++) {
                int4 v = sp[q];
                sj[q * 4 + 0] = v.x; sj[q * 4 + 1] = v.y;
                sj[q * 4 + 2] = v.z; sj[q * 4 + 3] = v.w;
            }
        }

        const int off = h * D + lo3 * 4;   // float offset within a feat row
        float4 acc = *reinterpret_cast<const float4*>(bias + off);

#pragma unroll
        for (int j = 0; j < DEG; j++) {
            const float4 v = *reinterpret_cast<const float4*>(
                feat + (size_t)sj[j] * HD + off);
            const float a = av[j];
            acc.x += a * v.x;
            acc.y += a * v.y;
            acc.z += a * v.z;
            acc.w += a * v.w;
        }

        *reinterpret_cast<float4*>(out + (size_t)(n0 + node) * HD + off) = acc;
    }
}

// ---------------------------------------------------------------------------
extern "C" void kernel_launch(void* const* d_in, const int* in_sizes, int n_in,
                              void* d_out, int out_size) {
    const float* feat   = (const float*)d_in[0];
    const float* attn_l = (const float*)d_in[1];
    const float* attn_r = (const float*)d_in[2];
    const float* bias   = (const float*)d_in[3];
    const int*   src    = (const int*)d_in[4];
    // d_in[5] = dst: structurally repeat(arange(N), DEG); not needed.

    float* out = (float*)d_out;

    // one warp per node, 8 nodes per 256-thread block
    int blocks1 = (N_NODES + 7) / 8;
    precompute_dots<<<blocks1, 256>>>(feat, attn_l, attn_r);

    gat_aggregate<<<N_NODES / NPB, 256>>>(feat, bias, src, out);
}